// round 16
// baseline (speedup 1.0000x reference)
#include <cuda_runtime.h>
#include <math.h>
#include <stdint.h>

// ===========================================================================
// StreamingSSMCell (B=8192, D=1024, DCONV=4) — persistent pipeline v2b
//   v2 retry: pre-round x/W_in/W_out to tf32 (RNA) outside the hot loop.
//   R14's "=f"-destination cvt was invalid (PTX requires .b32 dest for
//   cvt.*.tf32); this version uses the session-proven "=r" form everywhere.
//   Hot loop: 6 ldmatrix + 16 MMA per k-step, ZERO cvts.
//   d_out layout: [ out (B*D) | h_new (B*D) | new_buf (B*D*4) ]
// ===========================================================================

#define D_MODEL 1024
#define BATCH   8192
#define NSM     148

__device__ float g_g  [(size_t)BATCH * D_MODEL];            // g (tf32-rounded)
__device__ float g_xr [(size_t)BATCH * D_MODEL];            // x  tf32-rounded
__device__ float g_wir[(size_t)2 * D_MODEL * D_MODEL];      // W_in rounded
__device__ float g_wor[(size_t)D_MODEL * D_MODEL];          // W_out rounded
__device__ int   g_ctr[BATCH / 128];                        // G1 m-row counters

// ------------------------------ GEMM config --------------------------------
#define BM 128
#define BN 256
#define BK 32
#define KPAD 36
#define NTHREADS 512
#define NSTAGE 3
#define A_TILE_WORDS (BM * KPAD)
#define B_TILE_WORDS (BN * KPAD)
#define STAGE_WORDS  (A_TILE_WORDS + B_TILE_WORDS)
#define SMEM_BYTES   (NSTAGE * STAGE_WORDS * 4)      // 165888

// ------------------------------ PTX helpers --------------------------------
__device__ __forceinline__ uint32_t smem_u32(const void* p) {
    uint32_t a;
    asm("{ .reg .u64 t; cvta.to.shared.u64 t, %1; cvt.u32.u64 %0, t; }"
        : "=r"(a) : "l"(p));
    return a;
}

#define CP_ASYNC16(dst, src) \
    asm volatile("cp.async.cg.shared.global [%0], [%1], 16;" :: "r"(dst), "l"(src))
#define CP_ASYNC_COMMIT()   asm volatile("cp.async.commit_group;" ::: "memory")
#define CP_ASYNC_WAIT1()    asm volatile("cp.async.wait_group 1;" ::: "memory")
#define CP_ASYNC_WAIT_ALL() asm volatile("cp.async.wait_group 0;" ::: "memory")

// PROVEN form: b32 destination register (PTX requires .b32 for tf32 dest)
__device__ __forceinline__ float rna_bits(float x) {
    uint32_t r;
    asm("cvt.rna.tf32.f32 %0, %1;" : "=r"(r) : "f"(x));
    return __uint_as_float(r);
}

#define LDSM_X4(r0, r1, r2, r3, addr)                                          \
    asm volatile("ldmatrix.sync.aligned.m8n8.x4.shared.b16 {%0,%1,%2,%3}, [%4];" \
        : "=r"(r0), "=r"(r1), "=r"(r2), "=r"(r3) : "r"(addr))

#define MMA_TF32(c, a, b)                                                      \
    asm volatile("mma.sync.aligned.m16n8k8.row.col.f32.tf32.tf32.f32 "         \
        "{%0,%1,%2,%3}, {%4,%5,%6,%7}, {%8,%9}, {%0,%1,%2,%3};"                \
        : "+f"((c)[0]), "+f"((c)[1]), "+f"((c)[2]), "+f"((c)[3])               \
        : "r"((a)[0]), "r"((a)[1]), "r"((a)[2]), "r"((a)[3]),                  \
          "r"((b)[0]), "r"((b)[1]))

__device__ __forceinline__ float silu_f(float x) {
    return __fdividef(x, 1.0f + __expf(-x));
}

// --------------------------- aux kernels ------------------------------------
__global__ void zero_ctr(int n) {
    if (threadIdx.x < n) g_ctr[threadIdx.x] = 0;
}

__global__ void round_tf32(const float* __restrict__ in,
                           float* __restrict__ out, int n4)
{
    const int i = blockIdx.x * blockDim.x + threadIdx.x;
    if (i >= n4) return;
    float4 v = ((const float4*)in)[i];
    v.x = rna_bits(v.x); v.y = rna_bits(v.y);
    v.z = rna_bits(v.z); v.w = rna_bits(v.w);
    ((float4*)out)[i] = v;
}

// =========================== persistent pipeline ============================
__global__ __launch_bounds__(NTHREADS, 1)
void ssm_persistent(const float* __restrict__ x_r,      // [B, D] tf32-rounded
                    const float* __restrict__ Wi_r,     // [2D, D] rounded
                    const float* __restrict__ b_in,     // [2D]
                    const float* __restrict__ h,        // [B, D]
                    const float* __restrict__ conv_buf, // [B, D, 4]
                    const float* __restrict__ conv_w,   // [D, 4]
                    const float* __restrict__ conv_b,   // [D]
                    const float* __restrict__ Wo_r,     // [D, D] rounded
                    const float* __restrict__ b_out,    // [D]
                    float* __restrict__ out,            // [B, D]
                    float* __restrict__ out_hnew,       // [B, D]
                    float* __restrict__ out_newbuf)     // [B, D, 4]
{
    extern __shared__ float smem[];
    const uint32_t sbase = smem_u32(smem);
    const int tid  = threadIdx.x;
    const int lane = tid & 31;
    const int wid  = tid >> 5;
    const int wm = wid >> 3;             // 0..1
    const int wn = wid & 7;              // 0..7
    const int g  = lane >> 2;
    const int tg = lane & 3;
    const int T = D_MODEL / BK;          // 32

    uint32_t a_off[4];
    #pragma unroll
    for (int i = 0; i < 4; i++) {
        const int row = wm * 64 + i * 16 + (lane & 15);
        a_off[i] = (uint32_t)(row * KPAD + ((lane >> 4) << 2)) * 4u;
    }
    uint32_t b_off[2];
    #pragma unroll
    for (int jj = 0; jj < 2; jj++) {
        const int row = wn * 32 + jj * 16 + ((lane >> 4) << 3) + (lane & 7);
        b_off[jj] = (uint32_t)(row * KPAD + (((lane >> 3) & 1) << 2)) * 4u
                    + (uint32_t)(A_TILE_WORDS * 4);
    }

    const int mT  = BATCH / 128;               // 64
    const int nG1 = mT * (D_MODEL / 128);      // 512
    const int nG2 = mT * (D_MODEL / 256);      // 256
    const int nItems = nG1 + nG2;              // 768

    for (int item = blockIdx.x; item < nItems; item += NSM) {
        CP_ASYNC_WAIT_ALL();
        __syncthreads();

        float acc[4][4][4];
        #pragma unroll
        for (int i = 0; i < 4; i++)
            #pragma unroll
            for (int j = 0; j < 4; j++)
                #pragma unroll
                for (int r = 0; r < 4; r++) acc[i][j][r] = 0.0f;

        if (item < nG1) {
            // ================= G1 tile: xz pairs + fused epilogue ===========
            const int mt  = item >> 3;
            const int m0  = mt * 128;
            const int n0d = (item & 7) * 128;

            #define LOAD1(t) do {                                              \
                const uint32_t _s = sbase + ((t) % NSTAGE) * (STAGE_WORDS * 4);\
                _Pragma("unroll")                                              \
                for (int _q = 0; _q < 2; _q++) {                               \
                    const int _id = tid + _q * NTHREADS;                       \
                    const int _r = _id >> 3, _c = _id & 7;                     \
                    CP_ASYNC16(_s + _r * (KPAD * 4) + _c * 16,                 \
                        x_r + (size_t)(m0 + _r) * D_MODEL + (size_t)(t) * BK + _c * 4); \
                }                                                              \
                const uint32_t _sb = _s + A_TILE_WORDS * 4;                    \
                _Pragma("unroll")                                              \
                for (int _q = 0; _q < 4; _q++) {                               \
                    const int _id = tid + _q * NTHREADS;                       \
                    const int _r = _id >> 3, _c = _id & 7;                     \
                    const int _grow = ((_id & 8) ? D_MODEL : 0) + n0d + (_r >> 1); \
                    CP_ASYNC16(_sb + _r * (KPAD * 4) + _c * 16,                \
                        Wi_r + (size_t)_grow * D_MODEL + (size_t)(t) * BK + _c * 4); \
                }                                                              \
                CP_ASYNC_COMMIT();                                             \
            } while (0)

            LOAD1(0);
            LOAD1(1);

            for (int t = 0; t < T; t++) {
                CP_ASYNC_WAIT1();
                __syncthreads();
                if (t + 2 < T) { LOAD1(t + 2); } else { CP_ASYNC_COMMIT(); }

                const uint32_t st = sbase + (t % NSTAGE) * (STAGE_WORDS * 4);
                #pragma unroll
                for (int k0 = 0; k0 < BK; k0 += 8) {
                    const uint32_t kb = (uint32_t)(k0 * 4);
                    uint32_t af[4][4], bf[4][2];
                    #pragma unroll
                    for (int i = 0; i < 4; i++)
                        LDSM_X4(af[i][0], af[i][1], af[i][2], af[i][3],
                                st + a_off[i] + kb);
                    #pragma unroll
                    for (int jj = 0; jj < 2; jj++)
                        LDSM_X4(bf[jj * 2][0], bf[jj * 2][1],
                                bf[jj * 2 + 1][0], bf[jj * 2 + 1][1],
                                st + b_off[jj] + kb);
                    #pragma unroll
                    for (int i = 0; i < 4; i++)
                        #pragma unroll
                        for (int j = 0; j < 4; j++)
                            MMA_TF32(acc[i][j], af[i], bf[j]);
                }
            }
            #undef LOAD1

            // fused elementwise epilogue
            #pragma unroll
            for (int j = 0; j < 4; j++) {
                const int d = n0d + wn * 16 + j * 4 + tg;
                const float bi  = b_in[d];
                const float biz = b_in[D_MODEL + d];
                const float4 cw = *(const float4*)(conv_w + (size_t)d * 4);
                const float cbv = conv_b[d];
                const float tt = 2.302585092994046f
                               + (float)d * (7.600902459542082f - 2.302585092994046f)
                                 / (float)(D_MODEL - 1);
                const float dec = __expf(-__expf(-tt));

                #pragma unroll
                for (int i = 0; i < 4; i++) {
                    #pragma unroll
                    for (int e = 0; e < 2; e++) {
                        const int row = m0 + wm * 64 + i * 16 + g + e * 8;
                        const size_t idx = (size_t)row * D_MODEL + d;

                        const float xi = acc[i][j][e * 2 + 0] + bi;
                        const float zz = acc[i][j][e * 2 + 1] + biz;

                        const float4 cb = *(const float4*)(conv_buf + idx * 4);
                        float co = cb.y * cw.x + cb.z * cw.y + cb.w * cw.z
                                 + xi * cw.w + cbv;
                        co = silu_f(co);

                        const float hn = dec * h[idx] + (1.0f - dec) * co;

                        out_hnew[idx] = hn;
                        float4 nb;
                        nb.x = cb.y; nb.y = cb.z; nb.z = cb.w; nb.w = xi;
                        *(float4*)(out_newbuf + idx * 4) = nb;
                        g_g[idx] = rna_bits(hn * silu_f(zz));   // pre-rounded
                    }
                }
            }

            __syncthreads();
            if (tid == 0) {
                __threadfence();
                atomicAdd(&g_ctr[mt], 1);
            }
        } else {
            // ================= G2 tile: out = g @ W_out^T + b_out ===========
            const int r2 = item - nG1;
            const int mt = r2 >> 2;
            const int m0 = mt * 128;
            const int n0 = (r2 & 3) * 256;

            if (tid == 0) {
                while (atomicAdd(&g_ctr[mt], 0) < 8) { __nanosleep(200); }
                __threadfence();
            }
            __syncthreads();

            #define LOAD2(t) do {                                              \
                const uint32_t _s = sbase + ((t) % NSTAGE) * (STAGE_WORDS * 4);\
                _Pragma("unroll")                                              \
                for (int _q = 0; _q < 2; _q++) {                               \
                    const int _id = tid + _q * NTHREADS;                       \
                    const int _r = _id >> 3, _c = _id & 7;                     \
                    CP_ASYNC16(_s + _r * (KPAD * 4) + _c * 16,                 \
                        g_g + (size_t)(m0 + _r) * D_MODEL + (size_t)(t) * BK + _c * 4); \
                }                                                              \
                const uint32_t _sb = _s + A_TILE_WORDS * 4;                    \
                _Pragma("unroll")                                              \
                for (int _q = 0; _q < 4; _q++) {                               \
                    const int _id = tid + _q * NTHREADS;                       \
                    const int _r = _id >> 3, _c = _id & 7;                     \
                    CP_ASYNC16(_sb + _r * (KPAD * 4) + _c * 16,                \
                        Wo_r + (size_t)(n0 + _r) * D_MODEL + (size_t)(t) * BK + _c * 4); \
                }                                                              \
                CP_ASYNC_COMMIT();                                             \
            } while (0)

            LOAD2(0);
            LOAD2(1);

            for (int t = 0; t < T; t++) {
                CP_ASYNC_WAIT1();
                __syncthreads();
                if (t + 2 < T) { LOAD2(t + 2); } else { CP_ASYNC_COMMIT(); }

                const uint32_t st = sbase + (t % NSTAGE) * (STAGE_WORDS * 4);
                #pragma unroll
                for (int k0 = 0; k0 < BK; k0 += 8) {
                    const uint32_t kb = (uint32_t)(k0 * 4);
                    uint32_t af[4][4], bf[4][2];
                    #pragma unroll
                    for (int i = 0; i < 4; i++)
                        LDSM_X4(af[i][0], af[i][1], af[i][2], af[i][3],
                                st + a_off[i] + kb);
                    #pragma unroll
                    for (int jj = 0; jj < 2; jj++)
                        LDSM_X4(bf[jj * 2][0], bf[jj * 2][1],
                                bf[jj * 2 + 1][0], bf[jj * 2 + 1][1],
                                st + b_off[jj] + kb);
                    #pragma unroll
                    for (int i = 0; i < 4; i++)
                        #pragma unroll
                        for (int j = 0; j < 4; j++)
                            MMA_TF32(acc[i][j], af[i], bf[j]);
                }
            }
            #undef LOAD2

            #pragma unroll
            for (int j = 0; j < 4; j++) {
                const int col = n0 + wn * 32 + j * 8 + tg * 2;
                const float2 bb = *(const float2*)(b_out + col);
                #pragma unroll
                for (int i = 0; i < 4; i++) {
                    const int r0 = m0 + wm * 64 + i * 16 + g;
                    float2 v0;
                    v0.x = acc[i][j][0] + bb.x; v0.y = acc[i][j][1] + bb.y;
                    *(float2*)(out + (size_t)r0 * D_MODEL + col) = v0;
                    float2 v1;
                    v1.x = acc[i][j][2] + bb.x; v1.y = acc[i][j][3] + bb.y;
                    *(float2*)(out + (size_t)(r0 + 8) * D_MODEL + col) = v1;
                }
            }
        }
    }
}

// ------------------------------- launch ------------------------------------
extern "C" void kernel_launch(void* const* d_in, const int* in_sizes, int n_in,
                              void* d_out, int out_size)
{
    const float* x        = (const float*)d_in[0];
    const float* h        = (const float*)d_in[1];
    const float* conv_buf = (const float*)d_in[2];
    const float* W_in     = (const float*)d_in[3];
    const float* b_in     = (const float*)d_in[4];
    const float* conv_w   = (const float*)d_in[5];
    const float* conv_b   = (const float*)d_in[6];
    const float* W_out    = (const float*)d_in[7];
    const float* b_out    = (const float*)d_in[8];

    const int D = in_sizes[6];
    const int B = in_sizes[0] / D;
    const int twoD = in_sizes[4];

    float* out      = (float*)d_out;
    float* out_hnew = out + (size_t)B * D;
    float* out_nbuf = out + (size_t)2 * B * D;

    cudaFuncSetAttribute(ssm_persistent,
                         cudaFuncAttributeMaxDynamicSharedMemorySize, SMEM_BYTES);

    // pre-round GEMM inputs to tf32 bit patterns (RNA, proven "=r" cvt form)
    {
        int n4 = B * D / 4;
        round_tf32<<<(n4 + 255) / 256, 256>>>(x, g_xr, n4);
        n4 = twoD * D / 4;
        round_tf32<<<(n4 + 255) / 256, 256>>>(W_in, g_wir, n4);
        n4 = D * D / 4;
        round_tf32<<<(n4 + 255) / 256, 256>>>(W_out, g_wor, n4);
        zero_ctr<<<1, 64>>>(B / 128);
    }

    // one persistent kernel: G1 tiles then G2 tiles with dependency spin
    ssm_persistent<<<NSM, NTHREADS, SMEM_BYTES>>>(
        g_xr, g_wir, b_in, h, conv_buf, conv_w, conv_b, g_wor, b_out,
        out, out_hnew, out_nbuf);
}